// round 16
// baseline (speedup 1.0000x reference)
#include <cuda_runtime.h>
#include <cuda_fp16.h>
#include <cstdint>
#include <math.h>

// Problem constants
#define BB 4
#define SS 2048
#define DD 1024
#define HH 16
#define HD 64
#define MTOT (BB*SS)      // 8192
#define NQKV (3*DD)       // 3072
#define NHEADS (BB*HH)    // 64

// Q pre-scale: 1/sqrt(64) * log2(e)  (softmax done in exp2 domain)
#define QSCALE 0.1803368801111204f

// ---------------------------------------------------------------------------
// Scratch (static device globals — allowed). All single fp16.
// ---------------------------------------------------------------------------
__device__ __half g_X  [(size_t)MTOT*DD];
__device__ __half g_WqT[(size_t)NQKV*DD];
__device__ __half g_WoT[(size_t)DD*DD];
__device__ __half g_Q  [(size_t)NHEADS*SS*HD];   // scaled
__device__ __half g_K  [(size_t)NHEADS*SS*HD];
__device__ __half g_V  [(size_t)NHEADS*SS*HD];
__device__ __half g_O  [(size_t)MTOT*DD];

// ---------------------------------------------------------------------------
// PTX helpers
// ---------------------------------------------------------------------------
__device__ __forceinline__ uint32_t smem_u32(const void* p) {
    uint32_t a;
    asm("{ .reg .u64 t; cvta.to.shared.u64 t, %1; cvt.u32.u64 %0, t; }"
        : "=r"(a) : "l"(p));
    return a;
}
__device__ __forceinline__ void cp16(uint32_t dst, const void* src) {
    asm volatile("cp.async.cg.shared.global [%0], [%1], 16;\n"
                 :: "r"(dst), "l"(src));
}
#define CP_COMMIT() asm volatile("cp.async.commit_group;\n" ::: "memory")
#define CP_WAIT(n)  asm volatile("cp.async.wait_group %0;\n" :: "n"(n) : "memory")

__device__ __forceinline__ void ldsm4(uint32_t* r, uint32_t addr) {
    asm volatile("ldmatrix.sync.aligned.m8n8.x4.shared.b16 {%0,%1,%2,%3}, [%4];\n"
                 : "=r"(r[0]), "=r"(r[1]), "=r"(r[2]), "=r"(r[3]) : "r"(addr));
}
__device__ __forceinline__ void ldsm4t(uint32_t* r, uint32_t addr) {
    asm volatile("ldmatrix.sync.aligned.m8n8.x4.trans.shared.b16 {%0,%1,%2,%3}, [%4];\n"
                 : "=r"(r[0]), "=r"(r[1]), "=r"(r[2]), "=r"(r[3]) : "r"(addr));
}
__device__ __forceinline__ void mma_f16(float* c, const uint32_t* a,
                                        uint32_t b0, uint32_t b1) {
    asm volatile(
        "mma.sync.aligned.m16n8k16.row.col.f32.f16.f16.f32 "
        "{%0,%1,%2,%3}, {%4,%5,%6,%7}, {%8,%9}, {%0,%1,%2,%3};\n"
        : "+f"(c[0]), "+f"(c[1]), "+f"(c[2]), "+f"(c[3])
        : "r"(a[0]), "r"(a[1]), "r"(a[2]), "r"(a[3]), "r"(b0), "r"(b1));
}
__device__ __forceinline__ float ex2(float x) {
    float y;
    asm("ex2.approx.ftz.f32 %0, %1;" : "=f"(y) : "f"(x));
    return y;
}
__device__ __forceinline__ __half2 pack2h(float x, float y) {
    return __halves2half2(__float2half_rn(x), __float2half_rn(y));
}

// ---------------------------------------------------------------------------
// Fused prep: X -> fp16; Wqkv^T, Wo^T -> fp16.
// ---------------------------------------------------------------------------
__device__ __forceinline__ void do_transpose_cvt(
    const float* __restrict__ W, int K, int N, int bx, int by, int tid,
    __half* __restrict__ T)
{
    __shared__ float t[32][33];
    int nb = bx * 32, kb = by * 32;
    int tx = tid & 31, ty = tid >> 5;
    #pragma unroll
    for (int j = 0; j < 4; j++)
        t[ty + j*8][tx] = W[(size_t)(kb + ty + j*8) * N + nb + tx];
    __syncthreads();
    #pragma unroll
    for (int j = 0; j < 4; j++) {
        int n = nb + ty + j*8;
        T[(size_t)n * K + kb + tx] = __float2half_rn(t[tx][ty + j*8]);
    }
}

__global__ void __launch_bounds__(256) prep_kernel(
    const float* __restrict__ x, const float* __restrict__ Wqkv,
    const float* __restrict__ Wo)
{
    int bid = blockIdx.x;
    int tid = threadIdx.x;
    if (bid < 8192) {
        size_t i4 = ((size_t)bid * 256 + tid) * 4;
        float4 v = *(const float4*)(x + i4);
        *(__half2*)(g_X + i4)     = pack2h(v.x, v.y);
        *(__half2*)(g_X + i4 + 2) = pack2h(v.z, v.w);
    } else if (bid < 8192 + 3072) {
        int b = bid - 8192;
        do_transpose_cvt(Wqkv, DD, NQKV, b % 96, b / 96, tid, g_WqT);
    } else {
        int b = bid - 8192 - 3072;
        do_transpose_cvt(Wo, DD, DD, b % 32, b / 32, tid, g_WoT);
    }
}

// ---------------------------------------------------------------------------
// GEMM1: plain fp16, K=1024 (NCH=16). BM=BN=128, BK=64/stage, 256 threads,
// 3-stage, 2 CTAs/SM. Epilogue: +bqkv; Q *QSCALE; single fp16 scatter.
// ---------------------------------------------------------------------------
#define GPITCH 144
#define GSTG (128*GPITCH)
#define SMEM_GEMM (6*GSTG)

__global__ void __launch_bounds__(256, 2) gemm1_kernel(
    const __half* __restrict__ A, const __half* __restrict__ B,
    const float* __restrict__ bias)
{
    extern __shared__ char sm[];
    const uint32_t sb = smem_u32(sm);
    const int tid = threadIdx.x, wid = tid >> 5, lane = tid & 31;
    const int wm = wid >> 2, wn = wid & 3;
    const int m0 = blockIdx.y * 128, n0 = blockIdx.x * 128;

    float acc[4][4][4];
    #pragma unroll
    for (int i = 0; i < 4; i++)
        #pragma unroll
        for (int j = 0; j < 4; j++)
            #pragma unroll
            for (int e = 0; e < 4; e++) acc[i][j][e] = 0.0f;

    #define G1_ISSUE(c, st) do {                                               \
        int _kb = (c) * 64;                                                    \
        uint32_t _da = sb + (st) * GSTG;                                       \
        uint32_t _db = sb + 3*GSTG + (st) * GSTG;                              \
        _Pragma("unroll")                                                      \
        for (int _j = 0; _j < 4; _j++) {                                       \
            int _idx = tid + _j*256;                                           \
            int _row = _idx >> 3, _q = _idx & 7;                               \
            cp16(_da + _row*GPITCH + _q*16,                                    \
                 A + (size_t)(m0+_row)*DD + _kb + _q*8);                       \
            cp16(_db + _row*GPITCH + _q*16,                                    \
                 B + (size_t)(n0+_row)*DD + _kb + _q*8);                       \
        }                                                                      \
    } while (0)

    G1_ISSUE(0, 0); CP_COMMIT();
    G1_ISSUE(1, 1); CP_COMMIT();

    const int NCH = 16;
    int cur = 0;
    for (int c = 0; c < NCH; c++) {
        CP_WAIT(1);
        __syncthreads();
        int nxt = cur + 2 >= 3 ? cur - 1 : cur + 2;
        if (c + 2 < NCH) G1_ISSUE(c + 2, nxt);
        CP_COMMIT();

        uint32_t da = sb + cur * GSTG;
        uint32_t db = sb + 3*GSTG + cur * GSTG;

        #pragma unroll
        for (int kc2 = 0; kc2 < 2; kc2++) {
            uint32_t bfr[4][4];
            #pragma unroll
            for (int nt = 0; nt < 4; nt++)
                ldsm4(bfr[nt], db + (wn*32 + nt*8 + (lane & 7))*GPITCH
                               + kc2*64 + (lane >> 3)*16);
            #pragma unroll
            for (int kk = 0; kk < 2; kk++) {
                uint32_t afr[4][4];
                #pragma unroll
                for (int mt = 0; mt < 4; mt++)
                    ldsm4(afr[mt], da + (wm*64 + mt*16 + (lane & 15))*GPITCH
                                   + kc2*64 + kk*32 + (lane >> 4)*16);
                #pragma unroll
                for (int mt = 0; mt < 4; mt++)
                    #pragma unroll
                    for (int nt = 0; nt < 4; nt++)
                        mma_f16(acc[mt][nt], afr[mt], bfr[nt][kk*2], bfr[nt][kk*2+1]);
            }
        }
        cur = cur + 1 >= 3 ? 0 : cur + 1;
    }

    #pragma unroll
    for (int mt = 0; mt < 4; mt++) {
        #pragma unroll
        for (int rr = 0; rr < 2; rr++) {
            int row = wm*64 + mt*16 + (lane >> 2) + rr*8;
            int m = m0 + row;
            int b = m >> 11, s = m & 2047;
            #pragma unroll
            for (int nt = 0; nt < 4; nt++) {
                int col = n0 + wn*32 + nt*8 + 2*(lane & 3);
                float v0 = acc[mt][nt][rr*2]   + bias[col];
                float v1 = acc[mt][nt][rr*2+1] + bias[col+1];
                int h = col / 192;
                int t = col - h*192;
                int which = t >> 6;
                int hd = t & 63;
                size_t off = (((size_t)b*HH + h)*SS + s)*HD + hd;
                if (which == 0) {
                    *(__half2*)(g_Q + off) = pack2h(v0*QSCALE, v1*QSCALE);
                } else {
                    __half* dst = (which == 1) ? g_K : g_V;
                    *(__half2*)(dst + off) = pack2h(v0, v1);
                }
            }
        }
    }
}

// ---------------------------------------------------------------------------
// GEMM2: plain fp16, K=1024 (NCH=16). fp32 out.
// ---------------------------------------------------------------------------
__global__ void __launch_bounds__(256, 2) gemm2_kernel(
    const __half* __restrict__ A, const __half* __restrict__ B,
    const float* __restrict__ bias, float* __restrict__ out)
{
    extern __shared__ char sm[];
    const uint32_t sb = smem_u32(sm);
    const int tid = threadIdx.x, wid = tid >> 5, lane = tid & 31;
    const int wm = wid >> 2, wn = wid & 3;
    const int m0 = blockIdx.y * 128, n0 = blockIdx.x * 128;

    float acc[4][4][4];
    #pragma unroll
    for (int i = 0; i < 4; i++)
        #pragma unroll
        for (int j = 0; j < 4; j++)
            #pragma unroll
            for (int e = 0; e < 4; e++) acc[i][j][e] = 0.0f;

    G1_ISSUE(0, 0); CP_COMMIT();
    G1_ISSUE(1, 1); CP_COMMIT();

    const int NCH = 16;
    int cur = 0;
    for (int c = 0; c < NCH; c++) {
        CP_WAIT(1);
        __syncthreads();
        int nxt = cur + 2 >= 3 ? cur - 1 : cur + 2;
        if (c + 2 < NCH) G1_ISSUE(c + 2, nxt);
        CP_COMMIT();

        uint32_t da = sb + cur * GSTG;
        uint32_t db = sb + 3*GSTG + cur * GSTG;

        #pragma unroll
        for (int kc2 = 0; kc2 < 2; kc2++) {
            uint32_t bfr[4][4];
            #pragma unroll
            for (int nt = 0; nt < 4; nt++)
                ldsm4(bfr[nt], db + (wn*32 + nt*8 + (lane & 7))*GPITCH
                               + kc2*64 + (lane >> 3)*16);
            #pragma unroll
            for (int kk = 0; kk < 2; kk++) {
                uint32_t afr[4][4];
                #pragma unroll
                for (int mt = 0; mt < 4; mt++)
                    ldsm4(afr[mt], da + (wm*64 + mt*16 + (lane & 15))*GPITCH
                                   + kc2*64 + kk*32 + (lane >> 4)*16);
                #pragma unroll
                for (int mt = 0; mt < 4; mt++)
                    #pragma unroll
                    for (int nt = 0; nt < 4; nt++)
                        mma_f16(acc[mt][nt], afr[mt], bfr[nt][kk*2], bfr[nt][kk*2+1]);
            }
        }
        cur = cur + 1 >= 3 ? 0 : cur + 1;
    }

    #pragma unroll
    for (int mt = 0; mt < 4; mt++) {
        #pragma unroll
        for (int rr = 0; rr < 2; rr++) {
            int row = wm*64 + mt*16 + (lane >> 2) + rr*8;
            int m = m0 + row;
            #pragma unroll
            for (int nt = 0; nt < 4; nt++) {
                int col = n0 + wn*32 + nt*8 + 2*(lane & 3);
                float2 f2;
                f2.x = acc[mt][nt][rr*2]   + bias[col];
                f2.y = acc[mt][nt][rr*2+1] + bias[col+1];
                *(float2*)&out[(size_t)m*DD + col] = f2;
            }
        }
    }
}

// ---------------------------------------------------------------------------
// Flash attention fp16: Q tile 128 rows, KV tile 128 keys, 512 threads,
// 16 warps (8m x 2n), 1 CTA/SM (126KB smem, ~110 regs). Grid (16, 64).
// K/V streaming amortized over 2x Q rows vs R15.
// ---------------------------------------------------------------------------
#define APITCH 144
#define PPITCH 272
#define QS_OFF 0
#define QBUF   18432                 // Q: 128*144
#define KS_OFF QBUF                  // 18432
#define KBUF   18432                 // K buf: 128*144
#define VS_OFF (KS_OFF + 2*KBUF)     // 55296
#define VBUF   18432                 // V buf: 128*144
#define PS_OFF (VS_OFF + 2*VBUF)     // 92160
#define RED_OFF (PS_OFF + 128*PPITCH) // 126976
#define SMEM_ATTN (RED_OFF + 2048)   // 129024

__global__ void __launch_bounds__(512, 1) attn_kernel()
{
    const int qt = blockIdx.x;   // 0..15
    const int bh = blockIdx.y;   // 0..63
    extern __shared__ char sm[];
    const uint32_t sb = smem_u32(sm);
    const int tid = threadIdx.x, wid = tid >> 5, lane = tid & 31;
    const int wm = wid >> 1, wn = wid & 1;   // 8 x 2

    const size_t base = (size_t)bh * SS * HD;
    const __half* Qg = g_Q + base + (size_t)qt*128*HD;
    const __half* Kg = g_K + base;
    const __half* Vg = g_V + base;

    // ---- load Q: 128 rows x 128B, pitch 144 ----
    #pragma unroll
    for (int j = 0; j < 2; j++) {
        int idx = tid + j*512;
        int row = idx >> 3, q = idx & 7;
        cp16(sb + QS_OFF + row*APITCH + q*16, Qg + (size_t)row*HD + q*8);
    }

    #define LOAD_KV(t, buf) do {                                               \
        int _s0 = (t) * 128;                                                   \
        _Pragma("unroll")                                                      \
        for (int j = 0; j < 2; j++) {                                          \
            int _idx = tid + j*512;                                            \
            int _row = _idx >> 3, _q = _idx & 7;                               \
            cp16(sb + KS_OFF + (buf)*KBUF + _row*APITCH + _q*16,               \
                 Kg + (size_t)(_s0 + _row)*HD + _q*8);                         \
            cp16(sb + VS_OFF + (buf)*VBUF + _row*APITCH + _q*16,               \
                 Vg + (size_t)(_s0 + _row)*HD + _q*8);                         \
        }                                                                      \
    } while (0)

    LOAD_KV(0, 0);
    CP_COMMIT();

    float oacc[4][4];
    #pragma unroll
    for (int j = 0; j < 4; j++)
        #pragma unroll
        for (int e = 0; e < 4; e++) oacc[j][e] = 0.0f;
    float mst[2] = {-1e30f, -1e30f};
    float lst[2] = {0.0f, 0.0f};

    float* redm = (float*)(sm + RED_OFF);   // [2][128]
    float* reds = redm + 256;               // [2][128]
    const int rbase = wm*16 + (lane >> 2);  // 0..127

    for (int t = 0; t < 16; t++) {
        const int buf = t & 1;
        CP_WAIT(0);
        __syncthreads();
        if (t + 1 < 16) LOAD_KV(t + 1, buf ^ 1);
        CP_COMMIT();

        // ---- S = Q . K^T : warp covers 16 q-rows x keys wn*64..+64 ----
        float sacc[8][4];
        #pragma unroll
        for (int j = 0; j < 8; j++)
            #pragma unroll
            for (int e = 0; e < 4; e++) sacc[j][e] = 0.0f;

        const uint32_t kb = sb + KS_OFF + buf*KBUF;
        #pragma unroll
        for (int kc = 0; kc < 2; kc++) {
            uint32_t bfr[8][4];
            #pragma unroll
            for (int nt = 0; nt < 8; nt++)
                ldsm4(bfr[nt], kb + (wn*64 + nt*8 + (lane & 7))*APITCH
                               + kc*64 + (lane >> 3)*16);
            #pragma unroll
            for (int kk = 0; kk < 2; kk++) {
                uint32_t afr[4];
                ldsm4(afr, sb + QS_OFF + (wm*16 + (lane & 15))*APITCH
                           + kc*64 + kk*32 + (lane >> 4)*16);
                #pragma unroll
                for (int nt = 0; nt < 8; nt++)
                    mma_f16(sacc[nt], afr, bfr[nt][kk*2], bfr[nt][kk*2+1]);
            }
        }

        // ---- online softmax (exp2 domain) ----
        #pragma unroll
        for (int rr = 0; rr < 2; rr++) {
            float mx = sacc[0][rr*2];
            #pragma unroll
            for (int nt = 0; nt < 8; nt++) {
                mx = fmaxf(mx, sacc[nt][rr*2]);
                mx = fmaxf(mx, sacc[nt][rr*2+1]);
            }
            mx = fmaxf(mx, __shfl_xor_sync(0xffffffffu, mx, 1));
            mx = fmaxf(mx, __shfl_xor_sync(0xffffffffu, mx, 2));
            if ((lane & 3) == 0)
                redm[wn*128 + rbase + rr*8] = mx;
        }
        __syncthreads();

        float alpha[2];
        #pragma unroll
        for (int rr = 0; rr < 2; rr++) {
            int row = rbase + rr*8;
            float rm = fmaxf(redm[row], redm[128 + row]);
            float mn = fmaxf(mst[rr], rm);
            alpha[rr] = ex2(mst[rr] - mn);
            mst[rr] = mn;
            float sum = 0.0f;
            #pragma unroll
            for (int nt = 0; nt < 8; nt++) {
                float p0 = ex2(sacc[nt][rr*2]   - mn);
                float p1 = ex2(sacc[nt][rr*2+1] - mn);
                sacc[nt][rr*2] = p0; sacc[nt][rr*2+1] = p1;
                sum += p0 + p1;
            }
            sum += __shfl_xor_sync(0xffffffffu, sum, 1);
            sum += __shfl_xor_sync(0xffffffffu, sum, 2);
            if ((lane & 3) == 0)
                reds[wn*128 + row] = sum;
        }

        // write P fp16 (128 rows x 128 keys, pitch 272)
        #pragma unroll
        for (int rr = 0; rr < 2; rr++) {
            int row = rbase + rr*8;
            char* prow = sm + PS_OFF + row*PPITCH;
            #pragma unroll
            for (int nt = 0; nt < 8; nt++) {
                int klc = wn*64 + nt*8 + 2*(lane & 3);
                *(__half2*)(prow + klc*2) =
                    pack2h(sacc[nt][rr*2], sacc[nt][rr*2+1]);
            }
        }
        __syncthreads();

        // l update + O rescale
        #pragma unroll
        for (int rr = 0; rr < 2; rr++) {
            int row = rbase + rr*8;
            lst[rr] = lst[rr]*alpha[rr] + reds[row] + reds[128+row];
            #pragma unroll
            for (int nt = 0; nt < 4; nt++) {
                oacc[nt][rr*2]   *= alpha[rr];
                oacc[nt][rr*2+1] *= alpha[rr];
            }
        }

        // ---- O += P . V over 128 keys (k16 0..7), HD cols wn*32..+32 ----
        const uint32_t vb = sb + VS_OFF + buf*VBUF;
        #pragma unroll
        for (int k16 = 0; k16 < 8; k16++) {
            uint32_t afr[4];
            ldsm4(afr, sb + PS_OFF + (wm*16 + (lane & 15))*PPITCH
                       + k16*32 + (lane >> 4)*16);
            uint32_t bfr[2][4];
            #pragma unroll
            for (int ng = 0; ng < 2; ng++)
                ldsm4t(bfr[ng], vb + (k16*16 + (lane & 7) + ((lane >> 3) & 1)*8)*APITCH
                                + (wn*32 + ng*16 + (lane >> 4)*8)*2);
            #pragma unroll
            for (int nt = 0; nt < 4; nt++) {
                int ng = nt >> 1, nh = nt & 1;
                mma_f16(oacc[nt], afr, bfr[ng][nh*2], bfr[ng][nh*2+1]);
            }
        }
    }

    // ---- finalize ----
    #pragma unroll
    for (int rr = 0; rr < 2; rr++) {
        float inv = 1.0f / lst[rr];
        int row = rbase + rr*8;
        size_t off0 = base + (size_t)(qt*128 + row)*HD;
        #pragma unroll
        for (int nt = 0; nt < 4; nt++) {
            int hd = wn*32 + nt*8 + 2*(lane & 3);
            *(__half2*)(g_O + off0 + hd) =
                pack2h(oacc[nt][rr*2]*inv, oacc[nt][rr*2+1]*inv);
        }
    }
}

// ---------------------------------------------------------------------------
extern "C" void kernel_launch(void* const* d_in, const int* in_sizes, int n_in,
                              void* d_out, int out_size)
{
    const float* x    = (const float*)d_in[0];
    const float* Wqkv = (const float*)d_in[1];
    const float* bqkv = (const float*)d_in[2];
    const float* Wo   = (const float*)d_in[3];
    const float* bo   = (const float*)d_in[4];
    float* out = (float*)d_out;

    cudaFuncSetAttribute(gemm1_kernel,
                         cudaFuncAttributeMaxDynamicSharedMemorySize, SMEM_GEMM);
    cudaFuncSetAttribute(gemm2_kernel,
                         cudaFuncAttributeMaxDynamicSharedMemorySize, SMEM_GEMM);
    cudaFuncSetAttribute(attn_kernel,
                         cudaFuncAttributeMaxDynamicSharedMemorySize, SMEM_ATTN);

    __half *X, *WqT, *WoT, *O;
    cudaGetSymbolAddress((void**)&X,   g_X);
    cudaGetSymbolAddress((void**)&WqT, g_WqT);
    cudaGetSymbolAddress((void**)&WoT, g_WoT);
    cudaGetSymbolAddress((void**)&O,   g_O);

    prep_kernel<<<8192 + 3072 + 1024, 256>>>(x, Wqkv, Wo);

    gemm1_kernel<<<dim3(NQKV/128, MTOT/128), 256, SMEM_GEMM>>>(X, WqT, bqkv);

    attn_kernel<<<dim3(SS/128, NHEADS), 512, SMEM_ATTN>>>();

    gemm2_kernel<<<dim3(DD/128, MTOT/128), 256, SMEM_GEMM>>>(O, WoT, bo, out);
}

// round 17
// speedup vs baseline: 1.0092x; 1.0092x over previous
#include <cuda_runtime.h>
#include <cuda_fp16.h>
#include <cstdint>
#include <math.h>

// Problem constants
#define BB 4
#define SS 2048
#define DD 1024
#define HH 16
#define HD 64
#define MTOT (BB*SS)      // 8192
#define NQKV (3*DD)       // 3072
#define NHEADS (BB*HH)    // 64

// Q pre-scale: 1/sqrt(64) * log2(e)  (softmax done in exp2 domain)
#define QSCALE 0.1803368801111204f

// ---------------------------------------------------------------------------
// Scratch (static device globals — allowed). All single fp16.
// ---------------------------------------------------------------------------
__device__ __half g_X  [(size_t)MTOT*DD];
__device__ __half g_WqT[(size_t)NQKV*DD];
__device__ __half g_WoT[(size_t)DD*DD];
__device__ __half g_Q  [(size_t)NHEADS*SS*HD];   // scaled
__device__ __half g_K  [(size_t)NHEADS*SS*HD];
__device__ __half g_V  [(size_t)NHEADS*SS*HD];
__device__ __half g_O  [(size_t)MTOT*DD];

// ---------------------------------------------------------------------------
// PTX helpers
// ---------------------------------------------------------------------------
__device__ __forceinline__ uint32_t smem_u32(const void* p) {
    uint32_t a;
    asm("{ .reg .u64 t; cvta.to.shared.u64 t, %1; cvt.u32.u64 %0, t; }"
        : "=r"(a) : "l"(p));
    return a;
}
__device__ __forceinline__ void cp16(uint32_t dst, const void* src) {
    asm volatile("cp.async.cg.shared.global [%0], [%1], 16;\n"
                 :: "r"(dst), "l"(src));
}
#define CP_COMMIT() asm volatile("cp.async.commit_group;\n" ::: "memory")
#define CP_WAIT(n)  asm volatile("cp.async.wait_group %0;\n" :: "n"(n) : "memory")

__device__ __forceinline__ void ldsm4(uint32_t* r, uint32_t addr) {
    asm volatile("ldmatrix.sync.aligned.m8n8.x4.shared.b16 {%0,%1,%2,%3}, [%4];\n"
                 : "=r"(r[0]), "=r"(r[1]), "=r"(r[2]), "=r"(r[3]) : "r"(addr));
}
__device__ __forceinline__ void ldsm4t(uint32_t* r, uint32_t addr) {
    asm volatile("ldmatrix.sync.aligned.m8n8.x4.trans.shared.b16 {%0,%1,%2,%3}, [%4];\n"
                 : "=r"(r[0]), "=r"(r[1]), "=r"(r[2]), "=r"(r[3]) : "r"(addr));
}
__device__ __forceinline__ void mma_f16(float* c, const uint32_t* a,
                                        uint32_t b0, uint32_t b1) {
    asm volatile(
        "mma.sync.aligned.m16n8k16.row.col.f32.f16.f16.f32 "
        "{%0,%1,%2,%3}, {%4,%5,%6,%7}, {%8,%9}, {%0,%1,%2,%3};\n"
        : "+f"(c[0]), "+f"(c[1]), "+f"(c[2]), "+f"(c[3])
        : "r"(a[0]), "r"(a[1]), "r"(a[2]), "r"(a[3]), "r"(b0), "r"(b1));
}
__device__ __forceinline__ float ex2(float x) {
    float y;
    asm("ex2.approx.ftz.f32 %0, %1;" : "=f"(y) : "f"(x));
    return y;
}
__device__ __forceinline__ __half2 pack2h(float x, float y) {
    return __halves2half2(__float2half_rn(x), __float2half_rn(y));
}

// ---------------------------------------------------------------------------
// Fused prep: X -> fp16; Wqkv^T, Wo^T -> fp16.
// ---------------------------------------------------------------------------
__device__ __forceinline__ void do_transpose_cvt(
    const float* __restrict__ W, int K, int N, int bx, int by, int tid,
    __half* __restrict__ T)
{
    __shared__ float t[32][33];
    int nb = bx * 32, kb = by * 32;
    int tx = tid & 31, ty = tid >> 5;
    #pragma unroll
    for (int j = 0; j < 4; j++)
        t[ty + j*8][tx] = W[(size_t)(kb + ty + j*8) * N + nb + tx];
    __syncthreads();
    #pragma unroll
    for (int j = 0; j < 4; j++) {
        int n = nb + ty + j*8;
        T[(size_t)n * K + kb + tx] = __float2half_rn(t[tx][ty + j*8]);
    }
}

__global__ void __launch_bounds__(256) prep_kernel(
    const float* __restrict__ x, const float* __restrict__ Wqkv,
    const float* __restrict__ Wo)
{
    int bid = blockIdx.x;
    int tid = threadIdx.x;
    if (bid < 8192) {
        size_t i4 = ((size_t)bid * 256 + tid) * 4;
        float4 v = *(const float4*)(x + i4);
        *(__half2*)(g_X + i4)     = pack2h(v.x, v.y);
        *(__half2*)(g_X + i4 + 2) = pack2h(v.z, v.w);
    } else if (bid < 8192 + 3072) {
        int b = bid - 8192;
        do_transpose_cvt(Wqkv, DD, NQKV, b % 96, b / 96, tid, g_WqT);
    } else {
        int b = bid - 8192 - 3072;
        do_transpose_cvt(Wo, DD, DD, b % 32, b / 32, tid, g_WoT);
    }
}

// ---------------------------------------------------------------------------
// GEMM1: plain fp16, K=1024 (NCH=16). BM=BN=128, BK=64/stage, 256 threads,
// 3-stage, 2 CTAs/SM. Epilogue: +bqkv; Q *QSCALE; single fp16 scatter.
// ---------------------------------------------------------------------------
#define GPITCH 144
#define GSTG (128*GPITCH)
#define SMEM_GEMM (6*GSTG)

__global__ void __launch_bounds__(256, 2) gemm1_kernel(
    const __half* __restrict__ A, const __half* __restrict__ B,
    const float* __restrict__ bias)
{
    extern __shared__ char sm[];
    const uint32_t sb = smem_u32(sm);
    const int tid = threadIdx.x, wid = tid >> 5, lane = tid & 31;
    const int wm = wid >> 2, wn = wid & 3;
    const int m0 = blockIdx.y * 128, n0 = blockIdx.x * 128;

    float acc[4][4][4];
    #pragma unroll
    for (int i = 0; i < 4; i++)
        #pragma unroll
        for (int j = 0; j < 4; j++)
            #pragma unroll
            for (int e = 0; e < 4; e++) acc[i][j][e] = 0.0f;

    #define G1_ISSUE(c, st) do {                                               \
        int _kb = (c) * 64;                                                    \
        uint32_t _da = sb + (st) * GSTG;                                       \
        uint32_t _db = sb + 3*GSTG + (st) * GSTG;                              \
        _Pragma("unroll")                                                      \
        for (int _j = 0; _j < 4; _j++) {                                       \
            int _idx = tid + _j*256;                                           \
            int _row = _idx >> 3, _q = _idx & 7;                               \
            cp16(_da + _row*GPITCH + _q*16,                                    \
                 A + (size_t)(m0+_row)*DD + _kb + _q*8);                       \
            cp16(_db + _row*GPITCH + _q*16,                                    \
                 B + (size_t)(n0+_row)*DD + _kb + _q*8);                       \
        }                                                                      \
    } while (0)

    G1_ISSUE(0, 0); CP_COMMIT();
    G1_ISSUE(1, 1); CP_COMMIT();

    const int NCH = 16;
    int cur = 0;
    for (int c = 0; c < NCH; c++) {
        CP_WAIT(1);
        __syncthreads();
        int nxt = cur + 2 >= 3 ? cur - 1 : cur + 2;
        if (c + 2 < NCH) G1_ISSUE(c + 2, nxt);
        CP_COMMIT();

        uint32_t da = sb + cur * GSTG;
        uint32_t db = sb + 3*GSTG + cur * GSTG;

        #pragma unroll
        for (int kc2 = 0; kc2 < 2; kc2++) {
            uint32_t bfr[4][4];
            #pragma unroll
            for (int nt = 0; nt < 4; nt++)
                ldsm4(bfr[nt], db + (wn*32 + nt*8 + (lane & 7))*GPITCH
                               + kc2*64 + (lane >> 3)*16);
            #pragma unroll
            for (int kk = 0; kk < 2; kk++) {
                uint32_t afr[4][4];
                #pragma unroll
                for (int mt = 0; mt < 4; mt++)
                    ldsm4(afr[mt], da + (wm*64 + mt*16 + (lane & 15))*GPITCH
                                   + kc2*64 + kk*32 + (lane >> 4)*16);
                #pragma unroll
                for (int mt = 0; mt < 4; mt++)
                    #pragma unroll
                    for (int nt = 0; nt < 4; nt++)
                        mma_f16(acc[mt][nt], afr[mt], bfr[nt][kk*2], bfr[nt][kk*2+1]);
            }
        }
        cur = cur + 1 >= 3 ? 0 : cur + 1;
    }

    #pragma unroll
    for (int mt = 0; mt < 4; mt++) {
        #pragma unroll
        for (int rr = 0; rr < 2; rr++) {
            int row = wm*64 + mt*16 + (lane >> 2) + rr*8;
            int m = m0 + row;
            int b = m >> 11, s = m & 2047;
            #pragma unroll
            for (int nt = 0; nt < 4; nt++) {
                int col = n0 + wn*32 + nt*8 + 2*(lane & 3);
                float v0 = acc[mt][nt][rr*2]   + bias[col];
                float v1 = acc[mt][nt][rr*2+1] + bias[col+1];
                int h = col / 192;
                int t = col - h*192;
                int which = t >> 6;
                int hd = t & 63;
                size_t off = (((size_t)b*HH + h)*SS + s)*HD + hd;
                if (which == 0) {
                    *(__half2*)(g_Q + off) = pack2h(v0*QSCALE, v1*QSCALE);
                } else {
                    __half* dst = (which == 1) ? g_K : g_V;
                    *(__half2*)(dst + off) = pack2h(v0, v1);
                }
            }
        }
    }
}

// ---------------------------------------------------------------------------
// GEMM2: plain fp16, K=1024 (NCH=16). fp32 out.
// ---------------------------------------------------------------------------
__global__ void __launch_bounds__(256, 2) gemm2_kernel(
    const __half* __restrict__ A, const __half* __restrict__ B,
    const float* __restrict__ bias, float* __restrict__ out)
{
    extern __shared__ char sm[];
    const uint32_t sb = smem_u32(sm);
    const int tid = threadIdx.x, wid = tid >> 5, lane = tid & 31;
    const int wm = wid >> 2, wn = wid & 3;
    const int m0 = blockIdx.y * 128, n0 = blockIdx.x * 128;

    float acc[4][4][4];
    #pragma unroll
    for (int i = 0; i < 4; i++)
        #pragma unroll
        for (int j = 0; j < 4; j++)
            #pragma unroll
            for (int e = 0; e < 4; e++) acc[i][j][e] = 0.0f;

    G1_ISSUE(0, 0); CP_COMMIT();
    G1_ISSUE(1, 1); CP_COMMIT();

    const int NCH = 16;
    int cur = 0;
    for (int c = 0; c < NCH; c++) {
        CP_WAIT(1);
        __syncthreads();
        int nxt = cur + 2 >= 3 ? cur - 1 : cur + 2;
        if (c + 2 < NCH) G1_ISSUE(c + 2, nxt);
        CP_COMMIT();

        uint32_t da = sb + cur * GSTG;
        uint32_t db = sb + 3*GSTG + cur * GSTG;

        #pragma unroll
        for (int kc2 = 0; kc2 < 2; kc2++) {
            uint32_t bfr[4][4];
            #pragma unroll
            for (int nt = 0; nt < 4; nt++)
                ldsm4(bfr[nt], db + (wn*32 + nt*8 + (lane & 7))*GPITCH
                               + kc2*64 + (lane >> 3)*16);
            #pragma unroll
            for (int kk = 0; kk < 2; kk++) {
                uint32_t afr[4][4];
                #pragma unroll
                for (int mt = 0; mt < 4; mt++)
                    ldsm4(afr[mt], da + (wm*64 + mt*16 + (lane & 15))*GPITCH
                                   + kc2*64 + kk*32 + (lane >> 4)*16);
                #pragma unroll
                for (int mt = 0; mt < 4; mt++)
                    #pragma unroll
                    for (int nt = 0; nt < 4; nt++)
                        mma_f16(acc[mt][nt], afr[mt], bfr[nt][kk*2], bfr[nt][kk*2+1]);
            }
        }
        cur = cur + 1 >= 3 ? 0 : cur + 1;
    }

    #pragma unroll
    for (int mt = 0; mt < 4; mt++) {
        #pragma unroll
        for (int rr = 0; rr < 2; rr++) {
            int row = wm*64 + mt*16 + (lane >> 2) + rr*8;
            int m = m0 + row;
            #pragma unroll
            for (int nt = 0; nt < 4; nt++) {
                int col = n0 + wn*32 + nt*8 + 2*(lane & 3);
                float2 f2;
                f2.x = acc[mt][nt][rr*2]   + bias[col];
                f2.y = acc[mt][nt][rr*2+1] + bias[col+1];
                *(float2*)&out[(size_t)m*DD + col] = f2;
            }
        }
    }
}

// ---------------------------------------------------------------------------
// Flash attention fp16 (R15 shape): Q tile 64 rows, KV tile 128, 256 threads,
// 8 warps (4m x 2n), 2 CTAs/SM. Q fragments hoisted into registers (tile-
// invariant) — removes 4 A-LDSM per tile from the hot loop.
// ---------------------------------------------------------------------------
#define APITCH 144
#define PPITCH 272
#define QS_OFF 0
#define KS_OFF 9216                  // Q: 64*144
#define KBUF   18432                 // K buf: 128*144
#define VS_OFF (KS_OFF + 2*KBUF)     // 46080
#define VBUF   18432                 // V buf: 128*144
#define PS_OFF (VS_OFF + 2*VBUF)     // 82944
#define RED_OFF (PS_OFF + 64*PPITCH) // 100352
#define SMEM_ATTN (RED_OFF + 1024)   // 101376

__global__ void __launch_bounds__(256, 2) attn_kernel()
{
    const int qt = blockIdx.x;   // 0..31
    const int bh = blockIdx.y;   // 0..63
    extern __shared__ char sm[];
    const uint32_t sb = smem_u32(sm);
    const int tid = threadIdx.x, wid = tid >> 5, lane = tid & 31;
    const int wm = wid >> 1, wn = wid & 1;

    const size_t base = (size_t)bh * SS * HD;
    const __half* Qg = g_Q + base + (size_t)qt*64*HD;
    const __half* Kg = g_K + base;
    const __half* Vg = g_V + base;

    // ---- load Q: 64 rows x 128B, pitch 144 ----
    #pragma unroll
    for (int j = 0; j < 2; j++) {
        int idx = tid + j*256;
        int row = idx >> 3, q = idx & 7;
        cp16(sb + QS_OFF + row*APITCH + q*16, Qg + (size_t)row*HD + q*8);
    }

    #define LOAD_KV(t, buf) do {                                               \
        int _s0 = (t) * 128;                                                   \
        _Pragma("unroll")                                                      \
        for (int j = 0; j < 4; j++) {                                          \
            int _idx = tid + j*256;                                            \
            int _row = _idx >> 3, _q = _idx & 7;                               \
            cp16(sb + KS_OFF + (buf)*KBUF + _row*APITCH + _q*16,               \
                 Kg + (size_t)(_s0 + _row)*HD + _q*8);                         \
            cp16(sb + VS_OFF + (buf)*VBUF + _row*APITCH + _q*16,               \
                 Vg + (size_t)(_s0 + _row)*HD + _q*8);                         \
        }                                                                      \
    } while (0)

    LOAD_KV(0, 0);
    CP_COMMIT();
    CP_WAIT(0);
    __syncthreads();          // Q + tile 0 resident

    // ---- hoist Q fragments (tile-invariant): qfr[kc*2+kk] ----
    uint32_t qfr[4][4];
    #pragma unroll
    for (int kc = 0; kc < 2; kc++)
        #pragma unroll
        for (int kk = 0; kk < 2; kk++)
            ldsm4(qfr[kc*2+kk], sb + QS_OFF + (wm*16 + (lane & 15))*APITCH
                                + kc*64 + kk*32 + (lane >> 4)*16);

    // prefetch tile 1 (buf 1, untouched so far)
    LOAD_KV(1, 1);
    CP_COMMIT();

    float oacc[4][4];
    #pragma unroll
    for (int j = 0; j < 4; j++)
        #pragma unroll
        for (int e = 0; e < 4; e++) oacc[j][e] = 0.0f;
    float mst[2] = {-1e30f, -1e30f};
    float lst[2] = {0.0f, 0.0f};

    float* redm = (float*)(sm + RED_OFF);   // [2][64]
    float* reds = redm + 128;               // [2][64]
    const int rbase = wm*16 + (lane >> 2);

    for (int t = 0; t < 16; t++) {
        const int buf = t & 1;
        if (t > 0) {
            CP_WAIT(0);               // tile t landed
            __syncthreads();          // all warps done with buf^1 (tile t-1)
            if (t + 1 < 16) { LOAD_KV(t + 1, buf ^ 1); CP_COMMIT(); }
        }

        // ---- S = Q . K^T : warp covers keys wn*64..+64 (8 n-groups) ----
        float sacc[8][4];
        #pragma unroll
        for (int j = 0; j < 8; j++)
            #pragma unroll
            for (int e = 0; e < 4; e++) sacc[j][e] = 0.0f;

        const uint32_t kb = sb + KS_OFF + buf*KBUF;
        #pragma unroll
        for (int kc = 0; kc < 2; kc++) {
            uint32_t bfr[8][4];
            #pragma unroll
            for (int nt = 0; nt < 8; nt++)
                ldsm4(bfr[nt], kb + (wn*64 + nt*8 + (lane & 7))*APITCH
                               + kc*64 + (lane >> 3)*16);
            #pragma unroll
            for (int kk = 0; kk < 2; kk++) {
                #pragma unroll
                for (int nt = 0; nt < 8; nt++)
                    mma_f16(sacc[nt], qfr[kc*2+kk], bfr[nt][kk*2], bfr[nt][kk*2+1]);
            }
        }

        // ---- online softmax (exp2 domain), one update per 128 keys ----
        #pragma unroll
        for (int rr = 0; rr < 2; rr++) {
            float mx = sacc[0][rr*2];
            #pragma unroll
            for (int nt = 0; nt < 8; nt++) {
                mx = fmaxf(mx, sacc[nt][rr*2]);
                mx = fmaxf(mx, sacc[nt][rr*2+1]);
            }
            mx = fmaxf(mx, __shfl_xor_sync(0xffffffffu, mx, 1));
            mx = fmaxf(mx, __shfl_xor_sync(0xffffffffu, mx, 2));
            if ((lane & 3) == 0)
                redm[wn*64 + rbase + rr*8] = mx;
        }
        __syncthreads();

        float alpha[2];
        #pragma unroll
        for (int rr = 0; rr < 2; rr++) {
            int row = rbase + rr*8;
            float rm = fmaxf(redm[row], redm[64 + row]);
            float mn = fmaxf(mst[rr], rm);
            alpha[rr] = ex2(mst[rr] - mn);
            mst[rr] = mn;
            float sum = 0.0f;
            #pragma unroll
            for (int nt = 0; nt < 8; nt++) {
                float p0 = ex2(sacc[nt][rr*2]   - mn);
                float p1 = ex2(sacc[nt][rr*2+1] - mn);
                sacc[nt][rr*2] = p0; sacc[nt][rr*2+1] = p1;
                sum += p0 + p1;
            }
            sum += __shfl_xor_sync(0xffffffffu, sum, 1);
            sum += __shfl_xor_sync(0xffffffffu, sum, 2);
            if ((lane & 3) == 0)
                reds[wn*64 + row] = sum;
        }

        // write P fp16 (64 rows x 128 keys, pitch 272)
        #pragma unroll
        for (int rr = 0; rr < 2; rr++) {
            int row = rbase + rr*8;
            char* prow = sm + PS_OFF + row*PPITCH;
            #pragma unroll
            for (int nt = 0; nt < 8; nt++) {
                int klc = wn*64 + nt*8 + 2*(lane & 3);
                *(__half2*)(prow + klc*2) =
                    pack2h(sacc[nt][rr*2], sacc[nt][rr*2+1]);
            }
        }
        __syncthreads();

        // l update + O rescale (once per 128 keys)
        #pragma unroll
        for (int rr = 0; rr < 2; rr++) {
            int row = rbase + rr*8;
            lst[rr] = lst[rr]*alpha[rr] + reds[row] + reds[64+row];
            #pragma unroll
            for (int nt = 0; nt < 4; nt++) {
                oacc[nt][rr*2]   *= alpha[rr];
                oacc[nt][rr*2+1] *= alpha[rr];
            }
        }

        // ---- O += P . V over 128 keys (k16 0..7), HD cols wn*32..+32 ----
        const uint32_t vb = sb + VS_OFF + buf*VBUF;
        #pragma unroll
        for (int k16 = 0; k16 < 8; k16++) {
            uint32_t afr[4];
            ldsm4(afr, sb + PS_OFF + (wm*16 + (lane & 15))*PPITCH
                       + k16*32 + (lane >> 4)*16);
            uint32_t bfr[2][4];
            #pragma unroll
            for (int ng = 0; ng < 2; ng++)
                ldsm4t(bfr[ng], vb + (k16*16 + (lane & 7) + ((lane >> 3) & 1)*8)*APITCH
                                + (wn*32 + ng*16 + (lane >> 4)*8)*2);
            #pragma unroll
            for (int nt = 0; nt < 4; nt++) {
                int ng = nt >> 1, nh = nt & 1;
                mma_f16(oacc[nt], afr, bfr[ng][nh*2], bfr[ng][nh*2+1]);
            }
        }
    }

    // ---- finalize ----
    #pragma unroll
    for (int rr = 0; rr < 2; rr++) {
        float inv = 1.0f / lst[rr];
        int row = rbase + rr*8;
        size_t off0 = base + (size_t)(qt*64 + row)*HD;
        #pragma unroll
        for (int nt = 0; nt < 4; nt++) {
            int hd = wn*32 + nt*8 + 2*(lane & 3);
            *(__half2*)(g_O + off0 + hd) =
                pack2h(oacc[nt][rr*2]*inv, oacc[nt][rr*2+1]*inv);
        }
    }
}

// ---------------------------------------------------------------------------
extern "C" void kernel_launch(void* const* d_in, const int* in_sizes, int n_in,
                              void* d_out, int out_size)
{
    const float* x    = (const float*)d_in[0];
    const float* Wqkv = (const float*)d_in[1];
    const float* bqkv = (const float*)d_in[2];
    const float* Wo   = (const float*)d_in[3];
    const float* bo   = (const float*)d_in[4];
    float* out = (float*)d_out;

    cudaFuncSetAttribute(gemm1_kernel,
                         cudaFuncAttributeMaxDynamicSharedMemorySize, SMEM_GEMM);
    cudaFuncSetAttribute(gemm2_kernel,
                         cudaFuncAttributeMaxDynamicSharedMemorySize, SMEM_GEMM);
    cudaFuncSetAttribute(attn_kernel,
                         cudaFuncAttributeMaxDynamicSharedMemorySize, SMEM_ATTN);

    __half *X, *WqT, *WoT, *O;
    cudaGetSymbolAddress((void**)&X,   g_X);
    cudaGetSymbolAddress((void**)&WqT, g_WqT);
    cudaGetSymbolAddress((void**)&WoT, g_WoT);
    cudaGetSymbolAddress((void**)&O,   g_O);

    prep_kernel<<<8192 + 3072 + 1024, 256>>>(x, Wqkv, Wo);

    gemm1_kernel<<<dim3(NQKV/128, MTOT/128), 256, SMEM_GEMM>>>(X, WqT, bqkv);

    attn_kernel<<<dim3(SS/64, NHEADS), 256, SMEM_ATTN>>>();

    gemm2_kernel<<<dim3(DD/128, MTOT/128), 256, SMEM_GEMM>>>(O, WoT, bo, out);
}